// round 1
// baseline (speedup 1.0000x reference)
#include <cuda_runtime.h>

#define NB   8
#define CIN  512
#define COUT 1024
#define PP   2048
#define NH   8
#define DH   128

// ---------------- scratch (static device globals: no allocation allowed) -----
// g_Y layout: [proj(3)][b(8)][o(1024)][p(2048)]  (proj 0=Q, 1=K, 2=V)
__device__ float g_Y[(unsigned long long)3 * NB * COUT * PP];          // 192 MB
__device__ float g_S[(unsigned long long)NB * NH * PP * PP];           // 1 GiB
__device__ float g_scale[3][COUT];
__device__ float g_shift[3][COUT];

// ---------------- shared 128x128x8 SGEMM core --------------------------------
// C[m,n] = alpha * sum_k opA[m,k] * opB[k,n]
// AT=0: A is [M,K] row-major (lda = K-stride). AT=1: A stored [K,M] (A^T view).
// BT=0: B is [K,N] row-major.                 BT=1: B stored [N,K] (B^T view).
// Requires M,N multiples of 128 and K multiple of 8. blockDim = 256.
template <int AT, int BT>
__device__ __forceinline__ void gemm128(const float* __restrict__ A,
                                        const float* __restrict__ Bm,
                                        float* __restrict__ C,
                                        int K, int lda, int ldb, int ldc,
                                        float alpha)
{
    __shared__ float As[8][128];
    __shared__ float Bs[8][128];

    const int tid = threadIdx.x;
    const int tx = tid & 15;          // n direction (16)
    const int ty = tid >> 4;          // m direction (16)
    const int m0 = blockIdx.y * 128;
    const int n0 = blockIdx.x * 128;

    float acc[8][8];
#pragma unroll
    for (int r = 0; r < 8; r++)
#pragma unroll
        for (int c = 0; c < 8; c++) acc[r][c] = 0.0f;

    for (int k0 = 0; k0 < K; k0 += 8) {
#pragma unroll
        for (int i = 0; i < 4; i++) {
            int idx = tid + i * 256;            // 0..1023
            if (AT) {
                int kk = idx >> 7, mm = idx & 127;
                As[kk][mm] = A[(long)(k0 + kk) * lda + (m0 + mm)];
            } else {
                int mm = idx >> 3, kk = idx & 7;
                As[kk][mm] = A[(long)(m0 + mm) * lda + (k0 + kk)];
            }
            if (BT) {
                int nn = idx >> 3, kk = idx & 7;
                Bs[kk][nn] = Bm[(long)(n0 + nn) * ldb + (k0 + kk)];
            } else {
                int kk = idx >> 7, nn = idx & 127;
                Bs[kk][nn] = Bm[(long)(k0 + kk) * ldb + (n0 + nn)];
            }
        }
        __syncthreads();

#pragma unroll
        for (int kk = 0; kk < 8; kk++) {
            float4 a0 = *(const float4*)&As[kk][ty * 8];
            float4 a1 = *(const float4*)&As[kk][ty * 8 + 4];
            float4 b0 = *(const float4*)&Bs[kk][tx * 8];
            float4 b1 = *(const float4*)&Bs[kk][tx * 8 + 4];
            float a[8] = {a0.x, a0.y, a0.z, a0.w, a1.x, a1.y, a1.z, a1.w};
            float b[8] = {b0.x, b0.y, b0.z, b0.w, b1.x, b1.y, b1.z, b1.w};
#pragma unroll
            for (int r = 0; r < 8; r++)
#pragma unroll
                for (int c = 0; c < 8; c++) acc[r][c] += a[r] * b[c];
        }
        __syncthreads();
    }

#pragma unroll
    for (int r = 0; r < 8; r++) {
        float4 v0, v1;
        v0.x = alpha * acc[r][0]; v0.y = alpha * acc[r][1];
        v0.z = alpha * acc[r][2]; v0.w = alpha * acc[r][3];
        v1.x = alpha * acc[r][4]; v1.y = alpha * acc[r][5];
        v1.z = alpha * acc[r][6]; v1.w = alpha * acc[r][7];
        long off = (long)(m0 + ty * 8 + r) * ldc + (n0 + tx * 8);
        *(float4*)&C[off]     = v0;
        *(float4*)&C[off + 4] = v1;
    }
}

// ---------------- kernel 1: QKV projections (24 GEMMs 1024x2048x512) ---------
__global__ __launch_bounds__(256) void proj_kernel(const float* __restrict__ x,
                                                   const float* __restrict__ Wq,
                                                   const float* __restrict__ Wk,
                                                   const float* __restrict__ Wv)
{
    int z = blockIdx.z;
    int proj = z >> 3, b = z & 7;
    const float* W = (proj == 0) ? Wq : ((proj == 1) ? Wk : Wv);
    const float* Bx = x + (long)b * CIN * PP;
    float* C = g_Y + ((long)(proj * NB + b)) * COUT * PP;
    gemm128<0, 0>(W, Bx, C, CIN, CIN, PP, PP, 1.0f);
}

// ---------------- kernel 2: BN stats -> folded scale/shift -------------------
__global__ __launch_bounds__(256) void stats_kernel(const float* __restrict__ gq,
                                                    const float* __restrict__ bq,
                                                    const float* __restrict__ gk,
                                                    const float* __restrict__ bk,
                                                    const float* __restrict__ gv,
                                                    const float* __restrict__ bv)
{
    int ch   = blockIdx.x & (COUT - 1);
    int proj = blockIdx.x >> 10;
    const float* base = g_Y + ((long)proj * NB) * COUT * PP + (long)ch * PP;

    float s = 0.0f, sq = 0.0f;
    for (int b = 0; b < NB; b++) {
        const float* p = base + (long)b * COUT * PP;
        for (int i = threadIdx.x; i < PP; i += 256) {
            float v = p[i];
            s += v; sq += v * v;
        }
    }
#pragma unroll
    for (int o = 16; o; o >>= 1) {
        s  += __shfl_xor_sync(0xffffffffu, s, o);
        sq += __shfl_xor_sync(0xffffffffu, sq, o);
    }
    __shared__ float rs[8], rq[8];
    if ((threadIdx.x & 31) == 0) { rs[threadIdx.x >> 5] = s; rq[threadIdx.x >> 5] = sq; }
    __syncthreads();
    if (threadIdx.x == 0) {
        float S = 0.0f, Q = 0.0f;
#pragma unroll
        for (int w = 0; w < 8; w++) { S += rs[w]; Q += rq[w]; }
        const float inv_n = 1.0f / (float)(NB * PP);
        float mean = S * inv_n;
        float var  = Q * inv_n - mean * mean;
        const float* g  = (proj == 0) ? gq : ((proj == 1) ? gk : gv);
        const float* bb = (proj == 0) ? bq : ((proj == 1) ? bk : bv);
        float sc = g[ch] * rsqrtf(var + 1e-5f);
        g_scale[proj][ch] = sc;
        g_shift[proj][ch] = bb[ch] - mean * sc;
    }
}

// ---------------- kernel 3: apply BN + LeakyReLU in place --------------------
__global__ __launch_bounds__(256) void bn_apply_kernel()
{
    long v = (long)blockIdx.x * 256 + threadIdx.x;    // float4 index
    long e = v * 4;
    const long per_proj = (long)NB * COUT * PP;       // 16,777,216
    int proj = (int)(e / per_proj);
    long r   = e - (long)proj * per_proj;
    int ch   = (int)((r >> 11) & (COUT - 1));         // (r / 2048) % 1024
    float sc = g_scale[proj][ch], sh = g_shift[proj][ch];
    float4 y = *(float4*)&g_Y[e];
    y.x = sc * y.x + sh; y.x = (y.x < 0.0f) ? 0.1f * y.x : y.x;
    y.y = sc * y.y + sh; y.y = (y.y < 0.0f) ? 0.1f * y.y : y.y;
    y.z = sc * y.z + sh; y.z = (y.z < 0.0f) ? 0.1f * y.z : y.z;
    y.w = sc * y.w + sh; y.w = (y.w < 0.0f) ? 0.1f * y.w : y.w;
    *(float4*)&g_Y[e] = y;
}

// ---------------- kernel 4: S = K^T V / sqrt(dh) per (b,h) -------------------
__global__ __launch_bounds__(256) void attnS_kernel()
{
    int z = blockIdx.z;                 // bh = b*8 + h
    int b = z >> 3, h = z & 7;
    const float* A  = g_Y + ((long)(1 * NB + b) * COUT + h * DH) * PP;  // Khat [128 x 2048]
    const float* Bm = g_Y + ((long)(2 * NB + b) * COUT + h * DH) * PP;  // Vhat [128 x 2048]
    float* C = g_S + (long)z * PP * PP;
    gemm128<1, 0>(A, Bm, C, DH, PP, PP, PP, 0.08838834764831845f);      // 1/sqrt(128)
}

// ---------------- kernel 5: row softmax over j (2048) ------------------------
__global__ __launch_bounds__(256) void softmax_kernel()
{
    __shared__ float sh[8];
    long row = blockIdx.x;                               // 131072 rows
    float4* p = (float4*)(g_S + row * PP);
    int t = threadIdx.x;
    float4 a = p[t], b = p[t + 256];

    float m = fmaxf(fmaxf(fmaxf(a.x, a.y), fmaxf(a.z, a.w)),
                    fmaxf(fmaxf(b.x, b.y), fmaxf(b.z, b.w)));
#pragma unroll
    for (int o = 16; o; o >>= 1) m = fmaxf(m, __shfl_xor_sync(0xffffffffu, m, o));
    if ((t & 31) == 0) sh[t >> 5] = m;
    __syncthreads();
    m = sh[0];
#pragma unroll
    for (int w = 1; w < 8; w++) m = fmaxf(m, sh[w]);
    __syncthreads();

    a.x = expf(a.x - m); a.y = expf(a.y - m); a.z = expf(a.z - m); a.w = expf(a.w - m);
    b.x = expf(b.x - m); b.y = expf(b.y - m); b.z = expf(b.z - m); b.w = expf(b.w - m);
    float s = (a.x + a.y + a.z + a.w) + (b.x + b.y + b.z + b.w);
#pragma unroll
    for (int o = 16; o; o >>= 1) s += __shfl_xor_sync(0xffffffffu, s, o);
    if ((t & 31) == 0) sh[t >> 5] = s;
    __syncthreads();
    s = 0.0f;
#pragma unroll
    for (int w = 0; w < 8; w++) s += sh[w];

    float inv = 1.0f / s;
    a.x *= inv; a.y *= inv; a.z *= inv; a.w *= inv;
    b.x *= inv; b.y *= inv; b.z *= inv; b.w *= inv;
    p[t] = a; p[t + 256] = b;
}

// ---------------- kernel 6: out[c',i] = sum_j Qhat[c',j] * P[i,j] ------------
__global__ __launch_bounds__(256) void attnO_kernel(float* __restrict__ out)
{
    int z = blockIdx.z;
    int b = z >> 3, h = z & 7;
    const float* A  = g_Y + ((long)(0 * NB + b) * COUT + h * DH) * PP;  // Qhat [128 x 2048]
    const float* Bm = g_S + (long)z * PP * PP;                          // P [2048 x 2048], B^T view
    float* C = out + ((long)b * COUT + h * DH) * PP;
    gemm128<0, 1>(A, Bm, C, PP, PP, PP, PP, 1.0f);
}

// ---------------- launch -----------------------------------------------------
extern "C" void kernel_launch(void* const* d_in, const int* in_sizes, int n_in,
                              void* d_out, int out_size)
{
    (void)in_sizes; (void)n_in; (void)out_size;
    const float* x  = (const float*)d_in[0];
    const float* Wq = (const float*)d_in[1];
    const float* gq = (const float*)d_in[2];
    const float* bq = (const float*)d_in[3];
    const float* Wk = (const float*)d_in[4];
    const float* gk = (const float*)d_in[5];
    const float* bk = (const float*)d_in[6];
    const float* Wv = (const float*)d_in[7];
    const float* gv = (const float*)d_in[8];
    const float* bv = (const float*)d_in[9];
    float* out = (float*)d_out;

    // 1) Y = W x  (3 proj x 8 batches)
    proj_kernel<<<dim3(PP / 128, COUT / 128, 24), 256>>>(x, Wq, Wk, Wv);
    // 2) per-channel BN stats -> folded scale/shift
    stats_kernel<<<3 * COUT, 256>>>(gq, bq, gk, bk, gv, bv);
    // 3) BN + LeakyReLU in place
    bn_apply_kernel<<<(3u * NB * COUT * PP / 4) / 256, 256>>>();
    // 4) S = Khat^T Vhat / sqrt(dh)
    attnS_kernel<<<dim3(16, 16, NB * NH), 256>>>();
    // 5) softmax over last axis
    softmax_kernel<<<NB * NH * PP, 256>>>();
    // 6) out = Qhat P^T
    attnO_kernel<<<dim3(16, 1, NB * NH), 256>>>(out);
}

// round 3
// speedup vs baseline: 2.8138x; 2.8138x over previous
#include <cuda_runtime.h>
#include <cuda_bf16.h>
#include <cstdint>

#define NB   8
#define CIN  512
#define COUT 1024
#define PP   2048
#define NH   8
#define DH   128

typedef __nv_bfloat16 bf16;

// ---------------- device scratch (static: no allocation allowed) -------------
__device__ float g_Y[(size_t)3 * NB * COUT * PP];                    // 192 MB
__device__ float g_S[(size_t)NB * NH * PP * PP];                     // 1 GiB
__device__ float g_scale[3][COUT];
__device__ float g_shift[3][COUT];
__device__ bf16  g_Whi[3][COUT * CIN], g_Wlo[3][COUT * CIN];
__device__ bf16  g_xThi[(size_t)NB * PP * CIN], g_xTlo[(size_t)NB * PP * CIN];
__device__ bf16  g_Qhi[(size_t)NB * COUT * PP], g_Qlo[(size_t)NB * COUT * PP];
__device__ bf16  g_KThi[(size_t)NB * PP * COUT], g_KTlo[(size_t)NB * PP * COUT];
__device__ bf16  g_VThi[(size_t)NB * PP * COUT], g_VTlo[(size_t)NB * PP * COUT];
__device__ bf16  g_Phi[(size_t)NB * NH * PP * PP], g_Plo[(size_t)NB * NH * PP * PP];

// ---------------- PTX helpers (baseline PTX only: sm_80-class ops) -----------
__device__ __forceinline__ uint32_t smem_u32(const void* p) {
    uint32_t a;
    asm("{ .reg .u64 t; cvta.to.shared.u64 t, %1; cvt.u32.u64 %0, t; }" : "=r"(a) : "l"(p));
    return a;
}
__device__ __forceinline__ void cp16(uint32_t saddr, const void* g) {
    asm volatile("cp.async.cg.shared.global [%0], [%1], 16;" :: "r"(saddr), "l"(g));
}
#define CP_COMMIT() asm volatile("cp.async.commit_group;" ::: "memory")
template <int N>
__device__ __forceinline__ void cp_wait() {
    asm volatile("cp.async.wait_group %0;" :: "n"(N) : "memory");
}
__device__ __forceinline__ void lma4(uint32_t* r, uint32_t addr) {
    asm volatile("ldmatrix.sync.aligned.m8n8.x4.shared.b16 {%0,%1,%2,%3}, [%4];"
                 : "=r"(r[0]), "=r"(r[1]), "=r"(r[2]), "=r"(r[3]) : "r"(addr));
}
__device__ __forceinline__ void mma16816(float* d, const uint32_t* a, const uint32_t* b) {
    asm volatile("mma.sync.aligned.m16n8k16.row.col.f32.bf16.bf16.f32 "
                 "{%0,%1,%2,%3}, {%4,%5,%6,%7}, {%8,%9}, {%0,%1,%2,%3};"
                 : "+f"(d[0]), "+f"(d[1]), "+f"(d[2]), "+f"(d[3])
                 : "r"(a[0]), "r"(a[1]), "r"(a[2]), "r"(a[3]), "r"(b[0]), "r"(b[1]));
}

// SMEM: per stage: Ah, Al, Bh, Bl tiles of 128 rows x 32 bf16, rows padded to 80B
#define ROWB   80
#define MATB   (128 * ROWB)      // 10240
#define STAGEB (4 * MATB)        // 40960
#define OFF_AH 0
#define OFF_AL MATB
#define OFF_BH (2 * MATB)
#define OFF_BL (3 * MATB)
#define SMEM_BYTES (2 * STAGEB)  // 81920

// ---------------- mma.sync bf16-split GEMM core ------------------------------
// C[m0+m, n0+n] = alpha * sum_k (Ah+Al)[m,k] * (Bh+Bl)[n,k]   (128x128 tile)
// A row-major [M,K] (k-contiguous, lda), B row-major [N,K] (k-contiguous, ldb).
// blockDim = 256 (8 warps: wm in {0,1} x 64 rows, wn in {0..3} x 32 cols).
__device__ __forceinline__ void gemm_core(const bf16* __restrict__ Ah,
                                          const bf16* __restrict__ Al,
                                          const bf16* __restrict__ Bh,
                                          const bf16* __restrict__ Bl,
                                          size_t lda, size_t ldb, int K,
                                          float* __restrict__ C, size_t ldc,
                                          float alpha, int m0, int n0)
{
    extern __shared__ __align__(128) char smem[];
    const uint32_t sb = smem_u32(smem);
    const int tid = threadIdx.x;
    const int L = tid & 31;
    const int w = tid >> 5;
    const int wm = w >> 2, wn = w & 3;

    // loader mapping: 2 chunks (16B each) per matrix per thread
    const int ck0 = tid * 2, ck1 = tid * 2 + 1;
    const int lr0 = ck0 >> 2, lc0 = ck0 & 3;   // row 0..127, col-chunk 0..3
    const int lr1 = ck1 >> 2, lc1 = ck1 & 3;

    const bf16* pAh0 = Ah + (size_t)(m0 + lr0) * lda + lc0 * 8;
    const bf16* pAh1 = Ah + (size_t)(m0 + lr1) * lda + lc1 * 8;
    const bf16* pAl0 = Al + (size_t)(m0 + lr0) * lda + lc0 * 8;
    const bf16* pAl1 = Al + (size_t)(m0 + lr1) * lda + lc1 * 8;
    const bf16* pBh0 = Bh + (size_t)(n0 + lr0) * ldb + lc0 * 8;
    const bf16* pBh1 = Bh + (size_t)(n0 + lr1) * ldb + lc1 * 8;
    const bf16* pBl0 = Bl + (size_t)(n0 + lr0) * ldb + lc0 * 8;
    const bf16* pBl1 = Bl + (size_t)(n0 + lr1) * ldb + lc1 * 8;
    const uint32_t so0 = lr0 * ROWB + lc0 * 16;
    const uint32_t so1 = lr1 * ROWB + lc1 * 16;

    float acc[4][4][4];
#pragma unroll
    for (int mt = 0; mt < 4; mt++)
#pragma unroll
        for (int nt = 0; nt < 4; nt++)
#pragma unroll
            for (int i = 0; i < 4; i++) acc[mt][nt][i] = 0.0f;

    const int nch = K >> 5;

    // prefetch stage 0
    {
        uint32_t base = sb;
        cp16(base + OFF_AH + so0, pAh0); cp16(base + OFF_AH + so1, pAh1);
        cp16(base + OFF_AL + so0, pAl0); cp16(base + OFF_AL + so1, pAl1);
        cp16(base + OFF_BH + so0, pBh0); cp16(base + OFF_BH + so1, pBh1);
        cp16(base + OFF_BL + so0, pBl0); cp16(base + OFF_BL + so1, pBl1);
        CP_COMMIT();
    }

    // ldmatrix address components (within a stage)
    const uint32_t a_row = (uint32_t)(wm * 64 + ((L >> 3) & 1) * 8 + (L & 7));
    const uint32_t a_cc  = (uint32_t)(L >> 4);           // + kk/8
    const uint32_t b_row = (uint32_t)(wn * 32 + ((L >> 4) << 3) + (L & 7));
    const uint32_t b_cc  = (uint32_t)((L >> 3) & 1);     // + kk/8

    for (int ch = 0; ch < nch; ch++) {
        if (ch + 1 < nch) {
            uint32_t base = sb + ((ch + 1) & 1) * STAGEB;
            int kc = (ch + 1) * 32;
            cp16(base + OFF_AH + so0, pAh0 + kc); cp16(base + OFF_AH + so1, pAh1 + kc);
            cp16(base + OFF_AL + so0, pAl0 + kc); cp16(base + OFF_AL + so1, pAl1 + kc);
            cp16(base + OFF_BH + so0, pBh0 + kc); cp16(base + OFF_BH + so1, pBh1 + kc);
            cp16(base + OFF_BL + so0, pBl0 + kc); cp16(base + OFF_BL + so1, pBl1 + kc);
            CP_COMMIT();
            cp_wait<1>();
        } else {
            cp_wait<0>();
        }
        __syncthreads();

        uint32_t base = sb + (ch & 1) * STAGEB;
#pragma unroll
        for (int ks = 0; ks < 2; ks++) {       // kk = ks*16
            uint32_t afh[4][4], afl[4][4], bfh[4][2], bfl[4][2];
            uint32_t acol = (a_cc + ks * 2) * 16;
            uint32_t bcol = (b_cc + ks * 2) * 16;
#pragma unroll
            for (int mt = 0; mt < 4; mt++) {
                uint32_t ro = (a_row + mt * 16) * ROWB;
                lma4(afh[mt], base + OFF_AH + ro + acol);
                lma4(afl[mt], base + OFF_AL + ro + acol);
            }
#pragma unroll
            for (int np = 0; np < 2; np++) {
                uint32_t ro = (b_row + np * 16) * ROWB;
                uint32_t t4[4];
                lma4(t4, base + OFF_BH + ro + bcol);
                bfh[2 * np][0] = t4[0]; bfh[2 * np][1] = t4[1];
                bfh[2 * np + 1][0] = t4[2]; bfh[2 * np + 1][1] = t4[3];
                lma4(t4, base + OFF_BL + ro + bcol);
                bfl[2 * np][0] = t4[0]; bfl[2 * np][1] = t4[1];
                bfl[2 * np + 1][0] = t4[2]; bfl[2 * np + 1][1] = t4[3];
            }
#pragma unroll
            for (int mt = 0; mt < 4; mt++)
#pragma unroll
                for (int nt = 0; nt < 4; nt++) {
                    mma16816(acc[mt][nt], afh[mt], bfh[nt]);
                    mma16816(acc[mt][nt], afh[mt], bfl[nt]);
                    mma16816(acc[mt][nt], afl[mt], bfh[nt]);
                }
        }
        __syncthreads();
    }

    // epilogue: direct stores (thread t: rows g+0/g+8, col pair 2*(t&3))
    const int tg = L >> 2, tp = L & 3;
#pragma unroll
    for (int mt = 0; mt < 4; mt++) {
        int r0 = m0 + wm * 64 + mt * 16 + tg;
#pragma unroll
        for (int nt = 0; nt < 4; nt++) {
            int c = n0 + wn * 32 + nt * 8 + tp * 2;
            float2 v0 = make_float2(alpha * acc[mt][nt][0], alpha * acc[mt][nt][1]);
            float2 v1 = make_float2(alpha * acc[mt][nt][2], alpha * acc[mt][nt][3]);
            *(float2*)&C[(size_t)r0 * ldc + c]       = v0;
            *(float2*)&C[(size_t)(r0 + 8) * ldc + c] = v1;
        }
    }
}

// ---------------- GEMM wrappers ----------------------------------------------
__global__ __launch_bounds__(256) void proj_gemm(void) {
    int z = blockIdx.z, proj = z >> 3, b = z & 7;
    gemm_core(g_Whi[proj], g_Wlo[proj],
              g_xThi + (size_t)b * PP * CIN, g_xTlo + (size_t)b * PP * CIN,
              CIN, CIN, CIN,
              g_Y + (size_t)z * COUT * PP, PP, 1.0f,
              blockIdx.y * 128, blockIdx.x * 128);
}

__global__ __launch_bounds__(256) void attnS_gemm(void) {
    int z = blockIdx.z, b = z >> 3, h = z & 7;
    size_t off = (size_t)b * PP * COUT + (size_t)h * DH;
    gemm_core(g_KThi + off, g_KTlo + off, g_VThi + off, g_VTlo + off,
              COUT, COUT, DH,
              g_S + (size_t)z * PP * PP, PP, 0.08838834764831845f,
              blockIdx.y * 128, blockIdx.x * 128);
}

__global__ __launch_bounds__(256) void attnO_gemm(float* __restrict__ out) {
    int z = blockIdx.z, b = z >> 3, h = z & 7;
    size_t qoff = ((size_t)b * COUT + (size_t)h * DH) * PP;
    gemm_core(g_Qhi + qoff, g_Qlo + qoff,
              g_Phi + (size_t)z * PP * PP, g_Plo + (size_t)z * PP * PP,
              PP, PP, PP,
              out + qoff, PP, 1.0f, blockIdx.y * 128, blockIdx.x * 128);
}

// ---------------- conversions ------------------------------------------------
__device__ __forceinline__ void split1(float v, bf16& h, bf16& l) {
    h = __float2bfloat16(v);
    l = __float2bfloat16(v - __bfloat162float(h));
}
__device__ __forceinline__ void split4_store(float4 v, bf16* hi, bf16* lo) {
    bf16 h0, h1, h2, h3, l0, l1, l2, l3;
    split1(v.x, h0, l0); split1(v.y, h1, l1); split1(v.z, h2, l2); split1(v.w, h3, l3);
    __nv_bfloat162 hp0 = __halves2bfloat162(h0, h1), hp1 = __halves2bfloat162(h2, h3);
    __nv_bfloat162 lp0 = __halves2bfloat162(l0, l1), lp1 = __halves2bfloat162(l2, l3);
    ((__nv_bfloat162*)hi)[0] = hp0; ((__nv_bfloat162*)hi)[1] = hp1;
    ((__nv_bfloat162*)lo)[0] = lp0; ((__nv_bfloat162*)lo)[1] = lp1;
}

__global__ __launch_bounds__(256) void convert_w(const float* __restrict__ Wq,
                                                 const float* __restrict__ Wk,
                                                 const float* __restrict__ Wv) {
    int proj = blockIdx.z;
    const float* W = (proj == 0) ? Wq : ((proj == 1) ? Wk : Wv);
    size_t e = ((size_t)blockIdx.x * 256 + threadIdx.x) * 4;
    float4 v = *(const float4*)(W + e);
    split4_store(v, &g_Whi[proj][e], &g_Wlo[proj][e]);
}

__global__ __launch_bounds__(256) void transpose_x(const float* __restrict__ x) {
    __shared__ float t[32][33];
    int b = blockIdx.z;
    int p0 = blockIdx.x * 32, c0 = blockIdx.y * 32;
    int tx = threadIdx.x & 31, ty = threadIdx.x >> 5;   // 32x8
#pragma unroll
    for (int j = 0; j < 4; j++)
        t[ty + 8 * j][tx] = x[((size_t)b * CIN + c0 + ty + 8 * j) * PP + p0 + tx];
    __syncthreads();
#pragma unroll
    for (int j = 0; j < 4; j++) {
        float v = t[tx][ty + 8 * j];
        bf16 h, l; split1(v, h, l);
        size_t o = ((size_t)b * PP + p0 + ty + 8 * j) * CIN + c0 + tx;
        g_xThi[o] = h; g_xTlo[o] = l;
    }
}

// ---------------- BN stats ---------------------------------------------------
__global__ __launch_bounds__(256) void stats_kernel(const float* __restrict__ gq,
                                                    const float* __restrict__ bq,
                                                    const float* __restrict__ gk,
                                                    const float* __restrict__ bk,
                                                    const float* __restrict__ gv,
                                                    const float* __restrict__ bv) {
    int ch = blockIdx.x & (COUT - 1);
    int proj = blockIdx.x >> 10;
    const float* base = g_Y + ((size_t)proj * NB) * COUT * PP + (size_t)ch * PP;
    float s = 0.0f, sq = 0.0f;
    for (int b = 0; b < NB; b++) {
        const float* p = base + (size_t)b * COUT * PP;
        for (int i = threadIdx.x; i < PP; i += 256) {
            float v = p[i]; s += v; sq += v * v;
        }
    }
#pragma unroll
    for (int o = 16; o; o >>= 1) {
        s  += __shfl_xor_sync(0xffffffffu, s, o);
        sq += __shfl_xor_sync(0xffffffffu, sq, o);
    }
    __shared__ float rs[8], rq[8];
    if ((threadIdx.x & 31) == 0) { rs[threadIdx.x >> 5] = s; rq[threadIdx.x >> 5] = sq; }
    __syncthreads();
    if (threadIdx.x == 0) {
        float S = 0.0f, Q = 0.0f;
#pragma unroll
        for (int w = 0; w < 8; w++) { S += rs[w]; Q += rq[w]; }
        const float inv_n = 1.0f / (float)(NB * PP);
        float mean = S * inv_n;
        float var  = Q * inv_n - mean * mean;
        const float* g  = (proj == 0) ? gq : ((proj == 1) ? gk : gv);
        const float* bb = (proj == 0) ? bq : ((proj == 1) ? bk : bv);
        float sc = g[ch] * rsqrtf(var + 1e-5f);
        g_scale[proj][ch] = sc;
        g_shift[proj][ch] = bb[ch] - mean * sc;
    }
}

// ---------------- BN apply: Q path (keep [c][p] layout) ----------------------
__global__ __launch_bounds__(256) void bn_apply_q(void) {
    size_t e = ((size_t)blockIdx.x * 256 + threadIdx.x) * 4;
    int ch = (int)((e >> 11) & (COUT - 1));
    float sc = g_scale[0][ch], sh = g_shift[0][ch];
    float4 y = *(float4*)&g_Y[e];
    y.x = sc * y.x + sh; y.x = (y.x < 0.0f) ? 0.1f * y.x : y.x;
    y.y = sc * y.y + sh; y.y = (y.y < 0.0f) ? 0.1f * y.y : y.y;
    y.z = sc * y.z + sh; y.z = (y.z < 0.0f) ? 0.1f * y.z : y.z;
    y.w = sc * y.w + sh; y.w = (y.w < 0.0f) ? 0.1f * y.w : y.w;
    split4_store(y, &g_Qhi[e], &g_Qlo[e]);
}

// ---------------- BN apply + transpose: K/V paths ----------------------------
__global__ __launch_bounds__(256) void bn_apply_t(void) {
    __shared__ float t[32][33];
    int z = blockIdx.z;
    int proj = 1 + (z >> 3), b = z & 7;
    int p0 = blockIdx.x * 32, c0 = blockIdx.y * 32;
    int tx = threadIdx.x & 31, ty = threadIdx.x >> 5;
#pragma unroll
    for (int j = 0; j < 4; j++) {
        int c = c0 + ty + 8 * j;
        float sc = g_scale[proj][c], sh = g_shift[proj][c];
        float v = g_Y[(((size_t)proj * NB + b) * COUT + c) * PP + p0 + tx];
        v = sc * v + sh;
        v = (v < 0.0f) ? 0.1f * v : v;
        t[ty + 8 * j][tx] = v;
    }
    __syncthreads();
    bf16* Thi = (proj == 1) ? g_KThi : g_VThi;
    bf16* Tlo = (proj == 1) ? g_KTlo : g_VTlo;
#pragma unroll
    for (int j = 0; j < 4; j++) {
        float v = t[tx][ty + 8 * j];
        bf16 h, l; split1(v, h, l);
        size_t o = ((size_t)b * PP + p0 + ty + 8 * j) * COUT + c0 + tx;
        Thi[o] = h; Tlo[o] = l;
    }
}

// ---------------- softmax (fp32 in, bf16 hi/lo out) --------------------------
__global__ __launch_bounds__(256) void softmax_kernel(void) {
    __shared__ float sh[8];
    size_t row = blockIdx.x;
    float4* p = (float4*)(g_S + row * PP);
    int t = threadIdx.x;
    float4 a = p[t], b = p[t + 256];

    float m = fmaxf(fmaxf(fmaxf(a.x, a.y), fmaxf(a.z, a.w)),
                    fmaxf(fmaxf(b.x, b.y), fmaxf(b.z, b.w)));
#pragma unroll
    for (int o = 16; o; o >>= 1) m = fmaxf(m, __shfl_xor_sync(0xffffffffu, m, o));
    if ((t & 31) == 0) sh[t >> 5] = m;
    __syncthreads();
    m = sh[0];
#pragma unroll
    for (int w = 1; w < 8; w++) m = fmaxf(m, sh[w]);
    __syncthreads();

    a.x = expf(a.x - m); a.y = expf(a.y - m); a.z = expf(a.z - m); a.w = expf(a.w - m);
    b.x = expf(b.x - m); b.y = expf(b.y - m); b.z = expf(b.z - m); b.w = expf(b.w - m);
    float s = (a.x + a.y + a.z + a.w) + (b.x + b.y + b.z + b.w);
#pragma unroll
    for (int o = 16; o; o >>= 1) s += __shfl_xor_sync(0xffffffffu, s, o);
    if ((t & 31) == 0) sh[t >> 5] = s;
    __syncthreads();
    s = 0.0f;
#pragma unroll
    for (int w = 0; w < 8; w++) s += sh[w];

    float inv = 1.0f / s;
    a.x *= inv; a.y *= inv; a.z *= inv; a.w *= inv;
    b.x *= inv; b.y *= inv; b.z *= inv; b.w *= inv;
    size_t base = row * PP;
    split4_store(a, &g_Phi[base + (size_t)t * 4], &g_Plo[base + (size_t)t * 4]);
    split4_store(b, &g_Phi[base + (size_t)(t + 256) * 4], &g_Plo[base + (size_t)(t + 256) * 4]);
}

// ---------------- launch -----------------------------------------------------
extern "C" void kernel_launch(void* const* d_in, const int* in_sizes, int n_in,
                              void* d_out, int out_size)
{
    (void)in_sizes; (void)n_in; (void)out_size;
    const float* x  = (const float*)d_in[0];
    const float* Wq = (const float*)d_in[1];
    const float* gq = (const float*)d_in[2];
    const float* bq = (const float*)d_in[3];
    const float* Wk = (const float*)d_in[4];
    const float* gk = (const float*)d_in[5];
    const float* bk = (const float*)d_in[6];
    const float* Wv = (const float*)d_in[7];
    const float* gv = (const float*)d_in[8];
    const float* bv = (const float*)d_in[9];
    float* out = (float*)d_out;

    cudaFuncSetAttribute(proj_gemm,  cudaFuncAttributeMaxDynamicSharedMemorySize, SMEM_BYTES);
    cudaFuncSetAttribute(attnS_gemm, cudaFuncAttributeMaxDynamicSharedMemorySize, SMEM_BYTES);
    cudaFuncSetAttribute(attnO_gemm, cudaFuncAttributeMaxDynamicSharedMemorySize, SMEM_BYTES);

    // 1) input conversions: W -> bf16 hi/lo, x -> x^T bf16 hi/lo
    convert_w<<<dim3(COUT * CIN / 4 / 256, 1, 3), 256>>>(Wq, Wk, Wv);
    transpose_x<<<dim3(PP / 32, CIN / 32, NB), 256>>>(x);
    // 2) Y = W x (mma.sync, bf16 split)
    proj_gemm<<<dim3(PP / 128, COUT / 128, 24), 256, SMEM_BYTES>>>();
    // 3) BN stats -> folded scale/shift
    stats_kernel<<<3 * COUT, 256>>>(gq, bq, gk, bk, gv, bv);
    // 4) BN + LeakyReLU, emit Q (as-is) and K^T/V^T (transposed) bf16 hi/lo
    bn_apply_q<<<(unsigned)((size_t)NB * COUT * PP / 4 / 256), 256>>>();
    bn_apply_t<<<dim3(PP / 32, COUT / 32, 16), 256>>>();
    // 5) S = K^T V / sqrt(dh)
    attnS_gemm<<<dim3(16, 16, NB * NH), 256, SMEM_BYTES>>>();
    // 6) softmax rows -> P bf16 hi/lo
    softmax_kernel<<<NB * NH * PP, 256>>>();
    // 7) out = Q P^T
    attnO_gemm<<<dim3(16, 1, NB * NH), 256, SMEM_BYTES>>>(out);
}

// round 4
// speedup vs baseline: 3.5134x; 1.2486x over previous
#include <cuda_runtime.h>
#include <cuda_bf16.h>
#include <cstdint>

#define NB   8
#define CIN  512
#define COUT 1024
#define PP   2048
#define NH   8
#define DH   128

typedef __nv_bfloat16 bf16;

// ---------------- device scratch (static: no allocation allowed) -------------
__device__ float g_Y[(size_t)3 * NB * COUT * PP];                    // 192 MB
__device__ float g_scale[3][COUT];
__device__ float g_shift[3][COUT];
__device__ bf16  g_Whi[3][COUT * CIN], g_Wlo[3][COUT * CIN];
__device__ bf16  g_xThi[(size_t)NB * PP * CIN], g_xTlo[(size_t)NB * PP * CIN];
__device__ bf16  g_Qhi[(size_t)NB * COUT * PP], g_Qlo[(size_t)NB * COUT * PP];
__device__ bf16  g_KThi[(size_t)NB * PP * COUT], g_KTlo[(size_t)NB * PP * COUT];
__device__ bf16  g_VThi[(size_t)NB * PP * COUT], g_VTlo[(size_t)NB * PP * COUT];

// ---------------- PTX helpers (baseline PTX only) ----------------------------
__device__ __forceinline__ uint32_t smem_u32(const void* p) {
    uint32_t a;
    asm("{ .reg .u64 t; cvta.to.shared.u64 t, %1; cvt.u32.u64 %0, t; }" : "=r"(a) : "l"(p));
    return a;
}
__device__ __forceinline__ void cp16(uint32_t saddr, const void* g) {
    asm volatile("cp.async.cg.shared.global [%0], [%1], 16;" :: "r"(saddr), "l"(g));
}
#define CP_COMMIT() asm volatile("cp.async.commit_group;" ::: "memory")
template <int N>
__device__ __forceinline__ void cp_wait() {
    asm volatile("cp.async.wait_group %0;" :: "n"(N) : "memory");
}
__device__ __forceinline__ void lma4(uint32_t* r, uint32_t addr) {
    asm volatile("ldmatrix.sync.aligned.m8n8.x4.shared.b16 {%0,%1,%2,%3}, [%4];"
                 : "=r"(r[0]), "=r"(r[1]), "=r"(r[2]), "=r"(r[3]) : "r"(addr));
}
__device__ __forceinline__ void mma16816(float* d, const uint32_t* a, const uint32_t* b) {
    asm volatile("mma.sync.aligned.m16n8k16.row.col.f32.bf16.bf16.f32 "
                 "{%0,%1,%2,%3}, {%4,%5,%6,%7}, {%8,%9}, {%0,%1,%2,%3};"
                 : "+f"(d[0]), "+f"(d[1]), "+f"(d[2]), "+f"(d[3])
                 : "r"(a[0]), "r"(a[1]), "r"(a[2]), "r"(a[3]), "r"(b[0]), "r"(b[1]));
}

// =============================================================================
// Projection GEMM (unchanged from round 3): 128x128 tile, K-chunks of 32
// =============================================================================
#define ROWB   80
#define MATB   (128 * ROWB)
#define STAGEB (4 * MATB)
#define OFF_AH 0
#define OFF_AL MATB
#define OFF_BH (2 * MATB)
#define OFF_BL (3 * MATB)
#define SMEM_BYTES (2 * STAGEB)

__device__ __forceinline__ void gemm_core(const bf16* __restrict__ Ah,
                                          const bf16* __restrict__ Al,
                                          const bf16* __restrict__ Bh,
                                          const bf16* __restrict__ Bl,
                                          size_t lda, size_t ldb, int K,
                                          float* __restrict__ C, size_t ldc,
                                          float alpha, int m0, int n0)
{
    extern __shared__ __align__(128) char smem[];
    const uint32_t sb = smem_u32(smem);
    const int tid = threadIdx.x;
    const int L = tid & 31;
    const int w = tid >> 5;
    const int wm = w >> 2, wn = w & 3;

    const int ck0 = tid * 2, ck1 = tid * 2 + 1;
    const int lr0 = ck0 >> 2, lc0 = ck0 & 3;
    const int lr1 = ck1 >> 2, lc1 = ck1 & 3;

    const bf16* pAh0 = Ah + (size_t)(m0 + lr0) * lda + lc0 * 8;
    const bf16* pAh1 = Ah + (size_t)(m0 + lr1) * lda + lc1 * 8;
    const bf16* pAl0 = Al + (size_t)(m0 + lr0) * lda + lc0 * 8;
    const bf16* pAl1 = Al + (size_t)(m0 + lr1) * lda + lc1 * 8;
    const bf16* pBh0 = Bh + (size_t)(n0 + lr0) * ldb + lc0 * 8;
    const bf16* pBh1 = Bh + (size_t)(n0 + lr1) * ldb + lc1 * 8;
    const bf16* pBl0 = Bl + (size_t)(n0 + lr0) * ldb + lc0 * 8;
    const bf16* pBl1 = Bl + (size_t)(n0 + lr1) * ldb + lc1 * 8;
    const uint32_t so0 = lr0 * ROWB + lc0 * 16;
    const uint32_t so1 = lr1 * ROWB + lc1 * 16;

    float acc[4][4][4];
#pragma unroll
    for (int mt = 0; mt < 4; mt++)
#pragma unroll
        for (int nt = 0; nt < 4; nt++)
#pragma unroll
            for (int i = 0; i < 4; i++) acc[mt][nt][i] = 0.0f;

    const int nch = K >> 5;
    {
        uint32_t base = sb;
        cp16(base + OFF_AH + so0, pAh0); cp16(base + OFF_AH + so1, pAh1);
        cp16(base + OFF_AL + so0, pAl0); cp16(base + OFF_AL + so1, pAl1);
        cp16(base + OFF_BH + so0, pBh0); cp16(base + OFF_BH + so1, pBh1);
        cp16(base + OFF_BL + so0, pBl0); cp16(base + OFF_BL + so1, pBl1);
        CP_COMMIT();
    }

    const uint32_t a_row = (uint32_t)(wm * 64 + ((L >> 3) & 1) * 8 + (L & 7));
    const uint32_t a_cc  = (uint32_t)(L >> 4);
    const uint32_t b_row = (uint32_t)(wn * 32 + ((L >> 4) << 3) + (L & 7));
    const uint32_t b_cc  = (uint32_t)((L >> 3) & 1);

    for (int ch = 0; ch < nch; ch++) {
        if (ch + 1 < nch) {
            uint32_t base = sb + ((ch + 1) & 1) * STAGEB;
            int kc = (ch + 1) * 32;
            cp16(base + OFF_AH + so0, pAh0 + kc); cp16(base + OFF_AH + so1, pAh1 + kc);
            cp16(base + OFF_AL + so0, pAl0 + kc); cp16(base + OFF_AL + so1, pAl1 + kc);
            cp16(base + OFF_BH + so0, pBh0 + kc); cp16(base + OFF_BH + so1, pBh1 + kc);
            cp16(base + OFF_BL + so0, pBl0 + kc); cp16(base + OFF_BL + so1, pBl1 + kc);
            CP_COMMIT();
            cp_wait<1>();
        } else {
            cp_wait<0>();
        }
        __syncthreads();

        uint32_t base = sb + (ch & 1) * STAGEB;
#pragma unroll
        for (int ks = 0; ks < 2; ks++) {
            uint32_t afh[4][4], afl[4][4], bfh[4][2], bfl[4][2];
            uint32_t acol = (a_cc + ks * 2) * 16;
            uint32_t bcol = (b_cc + ks * 2) * 16;
#pragma unroll
            for (int mt = 0; mt < 4; mt++) {
                uint32_t ro = (a_row + mt * 16) * ROWB;
                lma4(afh[mt], base + OFF_AH + ro + acol);
                lma4(afl[mt], base + OFF_AL + ro + acol);
            }
#pragma unroll
            for (int np = 0; np < 2; np++) {
                uint32_t ro = (b_row + np * 16) * ROWB;
                uint32_t t4[4];
                lma4(t4, base + OFF_BH + ro + bcol);
                bfh[2 * np][0] = t4[0]; bfh[2 * np][1] = t4[1];
                bfh[2 * np + 1][0] = t4[2]; bfh[2 * np + 1][1] = t4[3];
                lma4(t4, base + OFF_BL + ro + bcol);
                bfl[2 * np][0] = t4[0]; bfl[2 * np][1] = t4[1];
                bfl[2 * np + 1][0] = t4[2]; bfl[2 * np + 1][1] = t4[3];
            }
#pragma unroll
            for (int mt = 0; mt < 4; mt++)
#pragma unroll
                for (int nt = 0; nt < 4; nt++) {
                    mma16816(acc[mt][nt], afh[mt], bfh[nt]);
                    mma16816(acc[mt][nt], afh[mt], bfl[nt]);
                    mma16816(acc[mt][nt], afl[mt], bfh[nt]);
                }
        }
        __syncthreads();
    }

    const int tg = L >> 2, tp = L & 3;
#pragma unroll
    for (int mt = 0; mt < 4; mt++) {
        int r0 = m0 + wm * 64 + mt * 16 + tg;
#pragma unroll
        for (int nt = 0; nt < 4; nt++) {
            int c = n0 + wn * 32 + nt * 8 + tp * 2;
            float2 v0 = make_float2(alpha * acc[mt][nt][0], alpha * acc[mt][nt][1]);
            float2 v1 = make_float2(alpha * acc[mt][nt][2], alpha * acc[mt][nt][3]);
            *(float2*)&C[(size_t)r0 * ldc + c]       = v0;
            *(float2*)&C[(size_t)(r0 + 8) * ldc + c] = v1;
        }
    }
}

__global__ __launch_bounds__(256) void proj_gemm(void) {
    int z = blockIdx.z, proj = z >> 3, b = z & 7;
    gemm_core(g_Whi[proj], g_Wlo[proj],
              g_xThi + (size_t)b * PP * CIN, g_xTlo + (size_t)b * PP * CIN,
              CIN, CIN, CIN,
              g_Y + (size_t)z * COUT * PP, PP, 1.0f,
              blockIdx.y * 128, blockIdx.x * 128);
}

// =============================================================================
// Fused flash attention: S = K^T V / sqrt(dh); P = softmax(S); O = P Q^T
// One CTA per (b, h, i-tile of 128). 8 warps (wm 2 x wn 4).
// =============================================================================
#define APITCH 272                       // 128 k-bf16 (256B) + 16B pad
#define TILEB  (128 * APITCH)            // 34816 per plane
#define SM_K   0                         // K tile hi/lo
#define SM_VQ  (2 * TILEB)               // V then Q tile hi/lo (shared)
#define SM_P   (4 * TILEB)               // P tile hi/lo (also fp32 out staging)
#define SM_RM  (6 * TILEB)               // row-max partials: 4 x 128 floats
#define SM_RS  (SM_RM + 2048)            // row-sum partials: 4 x 128 floats
#define SMEM_ATTN (SM_RS + 2048)         // 212992

__device__ __forceinline__ void load_tile(uint32_t sb, uint32_t off,
                                          const bf16* __restrict__ hi,
                                          const bf16* __restrict__ lo,
                                          size_t stride, int tid) {
#pragma unroll
    for (int i = 0; i < 8; i++) {
        int idx = tid + i * 256;
        int r = idx >> 4, cc = idx & 15;
        uint32_t so = off + r * APITCH + cc * 16;
        cp16(sb + so, hi + (size_t)r * stride + cc * 8);
        cp16(sb + so + TILEB, lo + (size_t)r * stride + cc * 8);
    }
}

__global__ __launch_bounds__(256, 1) void attn_fused(float* __restrict__ out) {
    extern __shared__ __align__(128) char smem[];
    const uint32_t sb = smem_u32(smem);
    const int tid = threadIdx.x;
    const int L = tid & 31, w = tid >> 5;
    const int wm = w >> 2, wn = w & 3;
    const int tg = L >> 2, tp = L & 3;
    const int it = blockIdx.x;
    const int z = blockIdx.y, b = z >> 3, h = z & 7;

    const bf16* Khi = g_KThi + ((size_t)b * PP + it * 128) * COUT + h * DH;
    const bf16* Klo = g_KTlo + ((size_t)b * PP + it * 128) * COUT + h * DH;
    const bf16* Vhi = g_VThi + (size_t)b * PP * COUT + h * DH;
    const bf16* Vlo = g_VTlo + (size_t)b * PP * COUT + h * DH;
    const bf16* Qhi = g_Qhi + ((size_t)b * COUT + h * DH) * PP;
    const bf16* Qlo = g_Qlo + ((size_t)b * COUT + h * DH) * PP;

    // K tile resident in SMEM for the whole kernel
    load_tile(sb, SM_K, Khi, Klo, COUT, tid);
    CP_COMMIT(); cp_wait<0>(); __syncthreads();

    const uint32_t a_row = (uint32_t)(wm * 64 + ((L >> 3) & 1) * 8 + (L & 7));
    const uint32_t a_cc  = (uint32_t)(L >> 4);
    const uint32_t b_row = (uint32_t)(wn * 32 + ((L >> 4) << 3) + (L & 7));
    const uint32_t b_cc  = (uint32_t)((L >> 3) & 1);

    const float cS = 1.4426950408889634f * 0.08838834764831845f;  // log2e / sqrt(128)

    float oacc[4][4][4];
    float mrow[4][2], lrow[4][2];
#pragma unroll
    for (int mt = 0; mt < 4; mt++) {
        mrow[mt][0] = mrow[mt][1] = -1e30f;
        lrow[mt][0] = lrow[mt][1] = 0.0f;
#pragma unroll
        for (int nt = 0; nt < 4; nt++)
#pragma unroll
            for (int i = 0; i < 4; i++) oacc[mt][nt][i] = 0.0f;
    }

    for (int jt = 0; jt < 16; jt++) {
        // ---- load V_J ----
        load_tile(sb, SM_VQ, Vhi + (size_t)jt * 128 * COUT, Vlo + (size_t)jt * 128 * COUT,
                  COUT, tid);
        CP_COMMIT(); cp_wait<0>(); __syncthreads();

        // ---- S = K_I^T V_J (k = dh = 128) ----
        float sacc[4][4][4];
#pragma unroll
        for (int mt = 0; mt < 4; mt++)
#pragma unroll
            for (int nt = 0; nt < 4; nt++)
#pragma unroll
                for (int i = 0; i < 4; i++) sacc[mt][nt][i] = 0.0f;

#pragma unroll
        for (int ks = 0; ks < 8; ks++) {
            uint32_t afh[4][4], afl[4][4], bfh[4][2], bfl[4][2];
            uint32_t acol = (a_cc + ks * 2) * 16;
            uint32_t bcol = (b_cc + ks * 2) * 16;
#pragma unroll
            for (int mt = 0; mt < 4; mt++) {
                uint32_t ro = (a_row + mt * 16) * APITCH;
                lma4(afh[mt], sb + SM_K + ro + acol);
                lma4(afl[mt], sb + SM_K + TILEB + ro + acol);
            }
#pragma unroll
            for (int np = 0; np < 2; np++) {
                uint32_t ro = (b_row + np * 16) * APITCH;
                uint32_t t4[4];
                lma4(t4, sb + SM_VQ + ro + bcol);
                bfh[2 * np][0] = t4[0]; bfh[2 * np][1] = t4[1];
                bfh[2 * np + 1][0] = t4[2]; bfh[2 * np + 1][1] = t4[3];
                lma4(t4, sb + SM_VQ + TILEB + ro + bcol);
                bfl[2 * np][0] = t4[0]; bfl[2 * np][1] = t4[1];
                bfl[2 * np + 1][0] = t4[2]; bfl[2 * np + 1][1] = t4[3];
            }
#pragma unroll
            for (int mt = 0; mt < 4; mt++)
#pragma unroll
                for (int nt = 0; nt < 4; nt++) {
                    mma16816(sacc[mt][nt], afh[mt], bfh[nt]);
                    mma16816(sacc[mt][nt], afh[mt], bfl[nt]);
                    mma16816(sacc[mt][nt], afl[mt], bfh[nt]);
                }
        }

        // scale into log2 domain, warp-level row maxes
        float wmax[4][2];
#pragma unroll
        for (int mt = 0; mt < 4; mt++) {
#pragma unroll
            for (int half = 0; half < 2; half++) {
                float mv = -1e30f;
#pragma unroll
                for (int nt = 0; nt < 4; nt++) {
                    sacc[mt][nt][2 * half]     *= cS;
                    sacc[mt][nt][2 * half + 1] *= cS;
                    mv = fmaxf(mv, fmaxf(sacc[mt][nt][2 * half], sacc[mt][nt][2 * half + 1]));
                }
                mv = fmaxf(mv, __shfl_xor_sync(0xffffffffu, mv, 1));
                mv = fmaxf(mv, __shfl_xor_sync(0xffffffffu, mv, 2));
                wmax[mt][half] = mv;
            }
        }
        if (tp == 0) {
#pragma unroll
            for (int mt = 0; mt < 4; mt++) {
                int r = wm * 64 + mt * 16 + tg;
                *(float*)(smem + SM_RM + (wn * 128 + r) * 4)     = wmax[mt][0];
                *(float*)(smem + SM_RM + (wn * 128 + r + 8) * 4) = wmax[mt][1];
            }
        }
        __syncthreads();                 // V reads done + partial maxes visible

        // prefetch Q_J into the V buffer (overlaps softmax math)
        load_tile(sb, SM_VQ, Qhi + (size_t)jt * 128, Qlo + (size_t)jt * 128, PP, tid);
        CP_COMMIT();

        // block row max, online update, exp, P write, partial sums
        float wsum[4][2];
#pragma unroll
        for (int mt = 0; mt < 4; mt++) {
#pragma unroll
            for (int half = 0; half < 2; half++) {
                int r = wm * 64 + mt * 16 + tg + half * 8;
                float bm = *(float*)(smem + SM_RM + r * 4);
                bm = fmaxf(bm, *(float*)(smem + SM_RM + (128 + r) * 4));
                bm = fmaxf(bm, *(float*)(smem + SM_RM + (256 + r) * 4));
                bm = fmaxf(bm, *(float*)(smem + SM_RM + (384 + r) * 4));
                float mn = fmaxf(mrow[mt][half], bm);
                float sc = exp2f(mrow[mt][half] - mn);
                mrow[mt][half] = mn;
                lrow[mt][half] *= sc;
                float rs = 0.0f;
#pragma unroll
                for (int nt = 0; nt < 4; nt++) {
                    oacc[mt][nt][2 * half]     *= sc;
                    oacc[mt][nt][2 * half + 1] *= sc;
                    float p0 = exp2f(sacc[mt][nt][2 * half]     - mn);
                    float p1 = exp2f(sacc[mt][nt][2 * half + 1] - mn);
                    rs += p0 + p1;
                    // split p into bf16 hi/lo and stash to SMEM
                    bf16 h0 = __float2bfloat16(p0);
                    bf16 h1 = __float2bfloat16(p1);
                    bf16 l0 = __float2bfloat16(p0 - __bfloat162float(h0));
                    bf16 l1 = __float2bfloat16(p1 - __bfloat162float(h1));
                    uint32_t col = wn * 32 + nt * 8 + 2 * tp;
                    uint32_t addr = r * APITCH + col * 2;
                    *(__nv_bfloat162*)(smem + SM_P + addr) = __halves2bfloat162(h0, h1);
                    *(__nv_bfloat162*)(smem + SM_P + TILEB + addr) = __halves2bfloat162(l0, l1);
                }
                rs += __shfl_xor_sync(0xffffffffu, rs, 1);
                rs += __shfl_xor_sync(0xffffffffu, rs, 2);
                wsum[mt][half] = rs;
            }
        }
        if (tp == 0) {
#pragma unroll
            for (int mt = 0; mt < 4; mt++) {
                int r = wm * 64 + mt * 16 + tg;
                *(float*)(smem + SM_RS + (wn * 128 + r) * 4)     = wsum[mt][0];
                *(float*)(smem + SM_RS + (wn * 128 + r + 8) * 4) = wsum[mt][1];
            }
        }
        cp_wait<0>();
        __syncthreads();                 // P + partial sums visible, Q loaded

#pragma unroll
        for (int mt = 0; mt < 4; mt++) {
#pragma unroll
            for (int half = 0; half < 2; half++) {
                int r = wm * 64 + mt * 16 + tg + half * 8;
                float bs = *(float*)(smem + SM_RS + r * 4)
                         + *(float*)(smem + SM_RS + (128 + r) * 4)
                         + *(float*)(smem + SM_RS + (256 + r) * 4)
                         + *(float*)(smem + SM_RS + (384 + r) * 4);
                lrow[mt][half] += bs;
            }
        }

        // ---- O += P Q^T (k = 128) ----
#pragma unroll
        for (int ks = 0; ks < 8; ks++) {
            uint32_t afh[4][4], afl[4][4], bfh[4][2], bfl[4][2];
            uint32_t acol = (a_cc + ks * 2) * 16;
            uint32_t bcol = (b_cc + ks * 2) * 16;
#pragma unroll
            for (int mt = 0; mt < 4; mt++) {
                uint32_t ro = (a_row + mt * 16) * APITCH;
                lma4(afh[mt], sb + SM_P + ro + acol);
                lma4(afl[mt], sb + SM_P + TILEB + ro + acol);
            }
#pragma unroll
            for (int np = 0; np < 2; np++) {
                uint32_t ro = (b_row + np * 16) * APITCH;
                uint32_t t4[4];
                lma4(t4, sb + SM_VQ + ro + bcol);
                bfh[2 * np][0] = t4[0]; bfh[2 * np][1] = t4[1];
                bfh[2 * np + 1][0] = t4[2]; bfh[2 * np + 1][1] = t4[3];
                lma4(t4, sb + SM_VQ + TILEB + ro + bcol);
                bfl[2 * np][0] = t4[0]; bfl[2 * np][1] = t4[1];
                bfl[2 * np + 1][0] = t4[2]; bfl[2 * np + 1][1] = t4[3];
            }
#pragma unroll
            for (int mt = 0; mt < 4; mt++)
#pragma unroll
                for (int nt = 0; nt < 4; nt++) {
                    mma16816(oacc[mt][nt], afh[mt], bfh[nt]);
                    mma16816(oacc[mt][nt], afh[mt], bfl[nt]);
                    mma16816(oacc[mt][nt], afl[mt], bfh[nt]);
                }
        }
        __syncthreads();                 // Q/P buffers free for next iteration
    }

    // ---- normalize by 1/l and transpose O[i][c] -> out[c][i] via SMEM ----
    float* fbuf = (float*)(smem + SM_P);       // 128 x 132 floats
#pragma unroll
    for (int mt = 0; mt < 4; mt++) {
#pragma unroll
        for (int half = 0; half < 2; half++) {
            int r = wm * 64 + mt * 16 + tg + half * 8;
            float inv = 1.0f / lrow[mt][half];
#pragma unroll
            for (int nt = 0; nt < 4; nt++) {
                int c = wn * 32 + nt * 8 + 2 * tp;
                fbuf[(size_t)c * 132 + r]       = oacc[mt][nt][2 * half] * inv;
                fbuf[(size_t)(c + 1) * 132 + r] = oacc[mt][nt][2 * half + 1] * inv;
            }
        }
    }
    __syncthreads();
    const size_t obase = ((size_t)b * COUT + h * DH) * PP + (size_t)it * 128;
#pragma unroll
    for (int rr = 0; rr < 16; rr++) {
        int r = w * 16 + rr;
        float4 v = *(float4*)&fbuf[(size_t)r * 132 + L * 4];
        *(float4*)&out[obase + (size_t)r * PP + L * 4] = v;
    }
}

// ---------------- conversions ------------------------------------------------
__device__ __forceinline__ void split1(float v, bf16& h, bf16& l) {
    h = __float2bfloat16(v);
    l = __float2bfloat16(v - __bfloat162float(h));
}
__device__ __forceinline__ void split4_store(float4 v, bf16* hi, bf16* lo) {
    bf16 h0, h1, h2, h3, l0, l1, l2, l3;
    split1(v.x, h0, l0); split1(v.y, h1, l1); split1(v.z, h2, l2); split1(v.w, h3, l3);
    ((__nv_bfloat162*)hi)[0] = __halves2bfloat162(h0, h1);
    ((__nv_bfloat162*)hi)[1] = __halves2bfloat162(h2, h3);
    ((__nv_bfloat162*)lo)[0] = __halves2bfloat162(l0, l1);
    ((__nv_bfloat162*)lo)[1] = __halves2bfloat162(l2, l3);
}

__global__ __launch_bounds__(256) void convert_w(const float* __restrict__ Wq,
                                                 const float* __restrict__ Wk,
                                                 const float* __restrict__ Wv) {
    int proj = blockIdx.z;
    const float* W = (proj == 0) ? Wq : ((proj == 1) ? Wk : Wv);
    size_t e = ((size_t)blockIdx.x * 256 + threadIdx.x) * 4;
    float4 v = *(const float4*)(W + e);
    split4_store(v, &g_Whi[proj][e], &g_Wlo[proj][e]);
}

__global__ __launch_bounds__(256) void transpose_x(const float* __restrict__ x) {
    __shared__ float t[32][33];
    int b = blockIdx.z;
    int p0 = blockIdx.x * 32, c0 = blockIdx.y * 32;
    int tx = threadIdx.x & 31, ty = threadIdx.x >> 5;
#pragma unroll
    for (int j = 0; j < 4; j++)
        t[ty + 8 * j][tx] = x[((size_t)b * CIN + c0 + ty + 8 * j) * PP + p0 + tx];
    __syncthreads();
#pragma unroll
    for (int j = 0; j < 4; j++) {
        float v = t[tx][ty + 8 * j];
        bf16 h, l; split1(v, h, l);
        size_t o = ((size_t)b * PP + p0 + ty + 8 * j) * CIN + c0 + tx;
        g_xThi[o] = h; g_xTlo[o] = l;
    }
}

// ---------------- BN stats ---------------------------------------------------
__global__ __launch_bounds__(256) void stats_kernel(const float* __restrict__ gq,
                                                    const float* __restrict__ bq,
                                                    const float* __restrict__ gk,
                                                    const float* __restrict__ bk,
                                                    const float* __restrict__ gv,
                                                    const float* __restrict__ bv) {
    int ch = blockIdx.x & (COUT - 1);
    int proj = blockIdx.x >> 10;
    const float* base = g_Y + ((size_t)proj * NB) * COUT * PP + (size_t)ch * PP;
    float s = 0.0f, sq = 0.0f;
    for (int b = 0; b < NB; b++) {
        const float* p = base + (size_t)b * COUT * PP;
        for (int i = threadIdx.x; i < PP; i += 256) {
            float v = p[i]; s += v; sq += v * v;
        }
    }
#pragma unroll
    for (int o = 16; o; o >>= 1) {
        s  += __shfl_xor_sync(0xffffffffu, s, o);
        sq += __shfl_xor_sync(0xffffffffu, sq, o);
    }
    __shared__ float rs[8], rq[8];
    if ((threadIdx.x & 31) == 0) { rs[threadIdx.x >> 5] = s; rq[threadIdx.x >> 5] = sq; }
    __syncthreads();
    if (threadIdx.x == 0) {
        float S = 0.0f, Q = 0.0f;
#pragma unroll
        for (int w = 0; w < 8; w++) { S += rs[w]; Q += rq[w]; }
        const float inv_n = 1.0f / (float)(NB * PP);
        float mean = S * inv_n;
        float var  = Q * inv_n - mean * mean;
        const float* g  = (proj == 0) ? gq : ((proj == 1) ? gk : gv);
        const float* bb = (proj == 0) ? bq : ((proj == 1) ? bk : bv);
        float sc = g[ch] * rsqrtf(var + 1e-5f);
        g_scale[proj][ch] = sc;
        g_shift[proj][ch] = bb[ch] - mean * sc;
    }
}

// ---------------- BN apply: Q path (keep [c][p] layout) ----------------------
__global__ __launch_bounds__(256) void bn_apply_q(void) {
    size_t e = ((size_t)blockIdx.x * 256 + threadIdx.x) * 4;
    int ch = (int)((e >> 11) & (COUT - 1));
    float sc = g_scale[0][ch], sh = g_shift[0][ch];
    float4 y = *(float4*)&g_Y[e];
    y.x = sc * y.x + sh; y.x = (y.x < 0.0f) ? 0.1f * y.x : y.x;
    y.y = sc * y.y + sh; y.y = (y.y < 0.0f) ? 0.1f * y.y : y.y;
    y.z = sc * y.z + sh; y.z = (y.z < 0.0f) ? 0.1f * y.z : y.z;
    y.w = sc * y.w + sh; y.w = (y.w < 0.0f) ? 0.1f * y.w : y.w;
    split4_store(y, &g_Qhi[e], &g_Qlo[e]);
}

// ---------------- BN apply + transpose: K/V paths ----------------------------
__global__ __launch_bounds__(256) void bn_apply_t(void) {
    __shared__ float t[32][33];
    int z = blockIdx.z;
    int proj = 1 + (z >> 3), b = z & 7;
    int p0 = blockIdx.x * 32, c0 = blockIdx.y * 32;
    int tx = threadIdx.x & 31, ty = threadIdx.x >> 5;
#pragma unroll
    for (int j = 0; j < 4; j++) {
        int c = c0 + ty + 8 * j;
        float sc = g_scale[proj][c], sh = g_shift[proj][c];
        float v = g_Y[(((size_t)proj * NB + b) * COUT + c) * PP + p0 + tx];
        v = sc * v + sh;
        v = (v < 0.0f) ? 0.1f * v : v;
        t[ty + 8 * j][tx] = v;
    }
    __syncthreads();
    bf16* Thi = (proj == 1) ? g_KThi : g_VThi;
    bf16* Tlo = (proj == 1) ? g_KTlo : g_VTlo;
#pragma unroll
    for (int j = 0; j < 4; j++) {
        float v = t[tx][ty + 8 * j];
        bf16 h, l; split1(v, h, l);
        size_t o = ((size_t)b * PP + p0 + ty + 8 * j) * COUT + c0 + tx;
        Thi[o] = h; Tlo[o] = l;
    }
}

// ---------------- launch -----------------------------------------------------
extern "C" void kernel_launch(void* const* d_in, const int* in_sizes, int n_in,
                              void* d_out, int out_size)
{
    (void)in_sizes; (void)n_in; (void)out_size;
    const float* x  = (const float*)d_in[0];
    const float* Wq = (const float*)d_in[1];
    const float* gq = (const float*)d_in[2];
    const float* bq = (const float*)d_in[3];
    const float* Wk = (const float*)d_in[4];
    const float* gk = (const float*)d_in[5];
    const float* bk = (const float*)d_in[6];
    const float* Wv = (const float*)d_in[7];
    const float* gv = (const float*)d_in[8];
    const float* bv = (const float*)d_in[9];
    float* out = (float*)d_out;

    cudaFuncSetAttribute(proj_gemm,  cudaFuncAttributeMaxDynamicSharedMemorySize, SMEM_BYTES);
    cudaFuncSetAttribute(attn_fused, cudaFuncAttributeMaxDynamicSharedMemorySize, SMEM_ATTN);

    // 1) input conversions
    convert_w<<<dim3(COUT * CIN / 4 / 256, 1, 3), 256>>>(Wq, Wk, Wv);
    transpose_x<<<dim3(PP / 32, CIN / 32, NB), 256>>>(x);
    // 2) Y = W x
    proj_gemm<<<dim3(PP / 128, COUT / 128, 24), 256, SMEM_BYTES>>>();
    // 3) BN stats
    stats_kernel<<<3 * COUT, 256>>>(gq, bq, gk, bk, gv, bv);
    // 4) BN + LeakyReLU, emit Q / K^T / V^T bf16 hi/lo
    bn_apply_q<<<(unsigned)((size_t)NB * COUT * PP / 4 / 256), 256>>>();
    bn_apply_t<<<dim3(PP / 32, COUT / 32, 16), 256>>>();
    // 5) fused S -> softmax -> O
    attn_fused<<<dim3(16, 64), 256, SMEM_ATTN>>>(out);
}